// round 2
// baseline (speedup 1.0000x reference)
#include <cuda_runtime.h>
#include <cstdint>

#define NN 50000
#define MM 24
#define AA 64
#define BB 32
#define KK 160   // 2A + B
#define OO 128   // 2A
#define EPSV 1e-5f
#define WARPS_A 8
#define NGROUPS (NN / 4)   // 12500, exact

// ---------------- scratch (static __device__, no allocation) ----------------
__device__ float g_y[(size_t)NN * OO];      // 25.6 MB: pre-BN1 activations
__device__ float g_core[(size_t)NN * AA];   // 12.8 MB: gated core pre-BN2
__device__ float g_stats1[2 * OO];          // [sum128 | sumsq128]
__device__ float g_stats2[2 * AA];          // [sum64  | sumsq64 ]
__device__ float g_bn1[2 * OO];             // [scale128 | shift128]
__device__ float g_bn2[2 * AA];             // [scale64  | shift64 ]

// ---------------- f32x2 packed-FMA helpers (sm_100+ PTX) ----------------
__device__ __forceinline__ unsigned long long pk2(float lo, float hi) {
    unsigned long long r;
    asm("mov.b64 %0, {%1, %2};" : "=l"(r) : "f"(lo), "f"(hi));
    return r;
}
__device__ __forceinline__ unsigned long long fma2(unsigned long long a,
                                                   unsigned long long b,
                                                   unsigned long long c) {
    unsigned long long d;
    asm("fma.rn.f32x2 %0, %1, %2, %3;" : "=l"(d) : "l"(a), "l"(b), "l"(c));
    return d;
}
__device__ __forceinline__ float2 upk2(unsigned long long v) {
    float2 r;
    asm("mov.b64 {%0, %1}, %2;" : "=f"(r.x), "=f"(r.y) : "l"(v));
    return r;
}

__device__ __forceinline__ float sigmoidf_(float x) {
    return 1.0f / (1.0f + __expf(-x));
}
__device__ __forceinline__ float softplusf_(float x) {
    // logaddexp(x, 0) = max(x,0) + log1p(exp(-|x|))  (stable both tails)
    return fmaxf(x, 0.0f) + log1pf(__expf(-fabsf(x)));
}

// ---------------- kernel 0: zero the stat accumulators ----------------
__global__ void k_zero() {
    int t = threadIdx.x;
    if (t < 2 * OO) g_stats1[t] = 0.0f;
    if (t < 2 * AA) g_stats2[t] = 0.0f;
}

// ---------------- kernel 1: fused gather + GEMV + BN1 stats ----------------
// smem layout (floats):
//   sW    [KK*OO]   = 20480   W transposed: sW[k*128 + o] = W[o*160 + k]
//   sb    [OO]      =   128
//   swb   [8*32]    =   256   per-warp bond weights w[m]
//   st    [8*4*KK]  =  5120   per-warp t-vectors for 4 nodes
//   sstat [2*OO]    =   256
#define SMEM_A_FLOATS (20480 + 128 + 256 + 5120 + 256)

__global__ void __launch_bounds__(256)
k_main(const float* __restrict__ atom,
       const float* __restrict__ nbrfea,
       const int* __restrict__ nbridx,      // int32! (JAX x64 disabled -> int64 request demotes)
       const float* __restrict__ bwi,
       const float* __restrict__ bwj,
       const float* __restrict__ W,
       const float* __restrict__ bias) {
    extern __shared__ float smem[];
    float* sW    = smem;
    float* sb    = sW + KK * OO;
    float* swb   = sb + OO;
    float* st    = swb + WARPS_A * 32;
    float* sstat = st + WARPS_A * 4 * KK;

    const int tid  = threadIdx.x;
    const int lane = tid & 31;
    const int warp = tid >> 5;

    // load W transposed + bias; zero block stat buffer
    for (int i = tid; i < KK * OO; i += 256) {
        int k = i >> 7, o = i & 127;
        sW[i] = W[o * KK + k];
    }
    if (tid < OO) sb[tid] = bias[tid];
    if (tid < 2 * OO) sstat[tid] = 0.0f;
    __syncthreads();

    // per-lane bias pairs (lane owns outputs 4l..4l+3)
    const float4 b4 = *(const float4*)(sb + 4 * lane);
    const unsigned long long b01 = pk2(b4.x, b4.y);
    const unsigned long long b23 = pk2(b4.z, b4.w);

    // per-lane BN1 stat partials for features 4l..4l+3
    float ssum[4] = {0.f, 0.f, 0.f, 0.f};
    float ssq[4]  = {0.f, 0.f, 0.f, 0.f};

    float* tw = st + warp * 4 * KK;

    for (int g = blockIdx.x * WARPS_A + warp; g < NGROUPS; g += gridDim.x * WARPS_A) {
        const int n0 = g * 4;

        // ---- phase 1: build t[160] for 4 nodes ----
        #pragma unroll
        for (int i = 0; i < 4; i++) {
            const int n = n0 + i;
            float* t = tw + i * KK;

            float wm = 0.0f;
            if (lane < MM) wm = bwi[n * MM + lane] * bwj[n * MM + lane];
            swb[warp * 32 + lane] = wm;
            float s = wm;
            #pragma unroll
            for (int o = 16; o; o >>= 1) s += __shfl_xor_sync(0xffffffffu, s, o);
            __syncwarp();

            float a0 = 0.f, a1 = 0.f, bacc = 0.f;
            const int* idxp = nbridx + (size_t)n * MM;
            const float* nrow = nbrfea + (size_t)n * MM * BB;
            #pragma unroll 4
            for (int m = 0; m < MM; m++) {
                const float wv = swb[warp * 32 + m];
                const int j = idxp[m];
                const float2 g2 = ((const float2*)(atom + (size_t)j * AA))[lane];
                a0 += wv * g2.x;
                a1 += wv * g2.y;
                bacc += wv * nrow[m * BB + lane];
            }
            const float2 aself = ((const float2*)(atom + (size_t)n * AA))[lane];
            ((float2*)t)[lane]        = make_float2(aself.x * s, aself.y * s); // t[0:64]
            ((float2*)(t + 64))[lane] = make_float2(a0, a1);                   // t[64:128]
            t[128 + lane] = bacc;                                              // t[128:160]
        }
        __syncwarp();

        // ---- phase 2: GEMV 160 -> 128 for 4 nodes (f32x2 packed) ----
        unsigned long long a01[4], a23[4];
        #pragma unroll
        for (int i = 0; i < 4; i++) { a01[i] = b01; a23[i] = b23; }

        #pragma unroll 4
        for (int k = 0; k < KK; k++) {
            const float4 wv = ((const float4*)(sW + k * OO))[lane];
            const unsigned long long w01 = pk2(wv.x, wv.y);
            const unsigned long long w23 = pk2(wv.z, wv.w);
            #pragma unroll
            for (int i = 0; i < 4; i++) {
                const float tk = tw[i * KK + k];
                const unsigned long long t2 = pk2(tk, tk);
                a01[i] = fma2(w01, t2, a01[i]);
                a23[i] = fma2(w23, t2, a23[i]);
            }
        }

        // ---- epilogue: store y, accumulate stats ----
        #pragma unroll
        for (int i = 0; i < 4; i++) {
            const float2 y01 = upk2(a01[i]);
            const float2 y23 = upk2(a23[i]);
            float4 yo = make_float4(y01.x, y01.y, y23.x, y23.y);
            *(float4*)(g_y + (size_t)(n0 + i) * OO + 4 * lane) = yo;
            ssum[0] += yo.x; ssq[0] += yo.x * yo.x;
            ssum[1] += yo.y; ssq[1] += yo.y * yo.y;
            ssum[2] += yo.z; ssq[2] += yo.z * yo.z;
            ssum[3] += yo.w; ssq[3] += yo.w * yo.w;
        }
        __syncwarp();
    }

    // ---- block-level stat reduction, then global atomics ----
    __syncthreads();
    #pragma unroll
    for (int c = 0; c < 4; c++) {
        atomicAdd(&sstat[4 * lane + c], ssum[c]);
        atomicAdd(&sstat[OO + 4 * lane + c], ssq[c]);
    }
    __syncthreads();
    if (tid < 2 * OO) atomicAdd(&g_stats1[tid], sstat[tid]);
}

// ---------------- kernel 2: finalize BN1 ----------------
__global__ void k_fin1(const float* __restrict__ gamma1,
                       const float* __restrict__ beta1) {
    int t = threadIdx.x;  // 128
    float mean = g_stats1[t] * (1.0f / NN);
    float var  = g_stats1[OO + t] * (1.0f / NN) - mean * mean;
    float sc = gamma1[t] * rsqrtf(var + EPSV);
    g_bn1[t] = sc;
    g_bn1[OO + t] = beta1[t] - mean * sc;
}

// ---------------- kernel 3: gate = sigmoid(h_f)*softplus(h_c) + BN2 stats ----------------
__global__ void __launch_bounds__(256)
k_gate() {
    __shared__ float sbn[2 * OO];
    __shared__ float sstat[2 * AA];
    int tid = threadIdx.x;
    sbn[tid] = g_bn1[tid];
    if (tid < 2 * AA) sstat[tid] = 0.0f;
    __syncthreads();

    const long long total = (long long)NN * AA;
    const long long stride = (long long)gridDim.x * 256;  // multiple of 64
    long long i0 = (long long)blockIdx.x * 256 + tid;
    const int f = (int)(i0 & 63);  // invariant under stride

    float psum = 0.f, psq = 0.f;
    for (long long i = i0; i < total; i += stride) {
        const long long n = i >> 6;
        const float yf = g_y[n * OO + f];
        const float yc = g_y[n * OO + AA + f];
        const float hf = fmaf(yf, sbn[f], sbn[OO + f]);
        const float hc = fmaf(yc, sbn[AA + f], sbn[OO + AA + f]);
        const float core = sigmoidf_(hf) * softplusf_(hc);
        g_core[i] = core;
        psum += core;
        psq += core * core;
    }
    atomicAdd(&sstat[f], psum);
    atomicAdd(&sstat[AA + f], psq);
    __syncthreads();
    if (tid < 2 * AA) atomicAdd(&g_stats2[tid], sstat[tid]);
}

// ---------------- kernel 4: finalize BN2 ----------------
__global__ void k_fin2(const float* __restrict__ gamma2,
                       const float* __restrict__ beta2) {
    int t = threadIdx.x;  // 64
    float mean = g_stats2[t] * (1.0f / NN);
    float var  = g_stats2[AA + t] * (1.0f / NN) - mean * mean;
    float sc = gamma2[t] * rsqrtf(var + EPSV);
    g_bn2[t] = sc;
    g_bn2[AA + t] = beta2[t] - mean * sc;
}

// ---------------- kernel 5: out = softplus(BN2(core)) ----------------
__global__ void __launch_bounds__(256)
k_out(float* __restrict__ out) {
    __shared__ float sbn[2 * AA];
    int tid = threadIdx.x;
    if (tid < 2 * AA) sbn[tid] = g_bn2[tid];
    __syncthreads();

    const long long total = (long long)NN * AA;
    const long long stride = (long long)gridDim.x * 256;
    long long i0 = (long long)blockIdx.x * 256 + tid;
    const int f = (int)(i0 & 63);
    for (long long i = i0; i < total; i += stride) {
        out[i] = softplusf_(fmaf(g_core[i], sbn[f], sbn[AA + f]));
    }
}

// ---------------- launcher ----------------
extern "C" void kernel_launch(void* const* d_in, const int* in_sizes, int n_in,
                              void* d_out, int out_size) {
    const float* atom   = (const float*)d_in[0];
    const float* nbrfea = (const float*)d_in[1];
    const int*   nbridx = (const int*)d_in[2];   // int32 on the wire
    const float* bwi    = (const float*)d_in[3];
    const float* bwj    = (const float*)d_in[4];
    const float* W      = (const float*)d_in[5];
    const float* bias   = (const float*)d_in[6];
    const float* gamma1 = (const float*)d_in[7];
    const float* beta1  = (const float*)d_in[8];
    const float* gamma2 = (const float*)d_in[9];
    const float* beta2  = (const float*)d_in[10];
    float*       out    = (float*)d_out;

    const int smemA = SMEM_A_FLOATS * sizeof(float);  // ~102.5 KB
    cudaFuncSetAttribute(k_main, cudaFuncAttributeMaxDynamicSharedMemorySize, smemA);

    k_zero<<<1, 384>>>();
    k_main<<<296, 256, smemA>>>(atom, nbrfea, nbridx, bwi, bwj, W, bias);
    k_fin1<<<1, 128>>>(gamma1, beta1);
    k_gate<<<592, 256>>>();
    k_fin2<<<1, 64>>>(gamma2, beta2);
    k_out<<<592, 256>>>(out);
}

// round 3
// speedup vs baseline: 1.4116x; 1.4116x over previous
#include <cuda_runtime.h>
#include <cstdint>

#define NN 50000
#define MM 24
#define AA 64
#define BB 32
#define KK 160   // 2A + B
#define OO 128   // 2A
#define EPSV 1e-5f

// ---------------- scratch (static __device__, no allocation) ----------------
__device__ float g_t[(size_t)NN * KK];      // 32 MB: concatenated gated features
__device__ float g_y[(size_t)NN * OO];      // 25.6 MB: pre-BN1 activations
__device__ float g_core[(size_t)NN * AA];   // 12.8 MB: gated core pre-BN2
__device__ float g_stats1[2 * OO];
__device__ float g_stats2[2 * AA];
__device__ float g_bn1[2 * OO];
__device__ float g_bn2[2 * AA];

// ---------------- f32x2 helpers ----------------
__device__ __forceinline__ unsigned long long fma2(unsigned long long a,
                                                   unsigned long long b,
                                                   unsigned long long c) {
    unsigned long long d;
    asm("fma.rn.f32x2 %0, %1, %2, %3;" : "=l"(d) : "l"(a), "l"(b), "l"(c));
    return d;
}
__device__ __forceinline__ float2 upk2(unsigned long long v) {
    float2 r;
    asm("mov.b64 {%0, %1}, %2;" : "=f"(r.x), "=f"(r.y) : "l"(v));
    return r;
}
__device__ __forceinline__ float sigmoidf_(float x) {
    return 1.0f / (1.0f + __expf(-x));
}
__device__ __forceinline__ float softplusf_(float x) {
    return fmaxf(x, 0.0f) + log1pf(__expf(-fabsf(x)));
}

// ---------------- kernel 0: zero stat accumulators ----------------
__global__ void k_zero() {
    int t = threadIdx.x;
    if (t < 2 * OO) g_stats1[t] = 0.0f;
    if (t < 2 * AA) g_stats2[t] = 0.0f;
}

// ---------------- kernel 1: gather/reduce -> t[n][160] ----------------
// one warp per node; m-loop fully unrolled -> ~24-48 outstanding loads/warp
__global__ void __launch_bounds__(256)
k_feat(const float* __restrict__ atom,
       const float* __restrict__ nbrfea,
       const int* __restrict__ nbridx,
       const float* __restrict__ bwi,
       const float* __restrict__ bwj) {
    __shared__ float sw[8][MM];
    __shared__ int   sj[8][MM];

    const int lane = threadIdx.x & 31;
    const int warp = threadIdx.x >> 5;
    const int n = blockIdx.x * 8 + warp;   // 6250*8 = 50000 exact

    float wm = 0.0f;
    if (lane < MM) {
        wm = bwi[(size_t)n * MM + lane] * bwj[(size_t)n * MM + lane];
        sw[warp][lane] = wm;
        sj[warp][lane] = nbridx[(size_t)n * MM + lane];
    }
    float s = wm;
    #pragma unroll
    for (int o = 16; o; o >>= 1) s += __shfl_xor_sync(0xffffffffu, s, o);
    __syncwarp();

    float a0 = 0.f, a1 = 0.f, bacc = 0.f;
    const float* nrow = nbrfea + (size_t)n * MM * BB;
    #pragma unroll
    for (int m = 0; m < MM; m++) {
        const float wv = sw[warp][m];
        const int j = sj[warp][m];
        const float2 g2 = ((const float2*)(atom + (size_t)j * AA))[lane];
        a0 = fmaf(wv, g2.x, a0);
        a1 = fmaf(wv, g2.y, a1);
        bacc = fmaf(wv, nrow[m * BB + lane], bacc);
    }

    const float2 aself = ((const float2*)(atom + (size_t)n * AA))[lane];
    float* t = g_t + (size_t)n * KK;
    ((float2*)t)[lane]        = make_float2(aself.x * s, aself.y * s); // t[0:64]
    ((float2*)(t + 64))[lane] = make_float2(a0, a1);                   // t[64:128]
    t[128 + lane] = bacc;                                              // t[128:160]
}

// ---------------- kernel 2: GEMM y = t @ W^T + b, fused BN1 stats ----------------
// k-pair packed f32x2: acc2 holds (even-k partial, odd-k partial) per output.
// sW4[p][q][0..3] = {W[2q][2p], W[2q][2p+1], W[2q+1][2p], W[2q+1][2p+1]}
//   -> ulonglong2 load gives w2 for outputs 2q and 2q+1 at k-pair p.
#define SMEM_G_FLOATS (80 * 256 + OO + 2 * OO)
#define GW 8

__global__ void __launch_bounds__(256)
k_gemm(const float* __restrict__ W, const float* __restrict__ bias) {
    extern __shared__ float smem[];
    float* sW4   = smem;               // 20480
    float* sb    = sW4 + 80 * 256;     // 128
    float* sstat = sb + OO;            // 256

    const int tid  = threadIdx.x;
    const int lane = tid & 31;
    const int warp = tid >> 5;

    for (int i = tid; i < 80 * 256; i += 256) {
        const int p = i >> 8, r = i & 255, q = r >> 2, c = r & 3;
        const int o = 2 * q + (c >> 1);
        const int k = 2 * p + (c & 1);
        sW4[i] = W[o * KK + k];
    }
    if (tid < OO) sb[tid] = bias[tid];
    if (tid < 2 * OO) sstat[tid] = 0.0f;
    __syncthreads();

    // lane owns outputs {2l, 2l+1, 64+2l, 64+2l+1}
    const float bo0 = sb[2 * lane], bo1 = sb[2 * lane + 1];
    const float bo2 = sb[AA + 2 * lane], bo3 = sb[AA + 2 * lane + 1];

    float ssum[4] = {0.f, 0.f, 0.f, 0.f};
    float ssq[4]  = {0.f, 0.f, 0.f, 0.f};

    for (int g = blockIdx.x * GW + warp; g < NN / 4; g += gridDim.x * GW) {
        const int n0 = g * 4;

        unsigned long long acc[4][4];
        #pragma unroll
        for (int i = 0; i < 4; i++)
            #pragma unroll
            for (int c = 0; c < 4; c++) acc[i][c] = 0ull;

        #pragma unroll 2
        for (int pp = 0; pp < 40; pp++) {
            // W for k-pairs p=2pp and p=2pp+1
            const ulonglong2* wp0 = (const ulonglong2*)(sW4 + (2 * pp) * 256);
            const ulonglong2* wp1 = (const ulonglong2*)(sW4 + (2 * pp + 1) * 256);
            const ulonglong2 wA = wp0[lane];        // outputs 2l,2l+1   @ p=2pp
            const ulonglong2 wB = wp0[32 + lane];   // outputs 64+2l,+1  @ p=2pp
            const ulonglong2 wC = wp1[lane];        // outputs 2l,2l+1   @ p=2pp+1
            const ulonglong2 wD = wp1[32 + lane];   // outputs 64+2l,+1  @ p=2pp+1

            #pragma unroll
            for (int i = 0; i < 4; i++) {
                // t k-pairs (t[4pp],t[4pp+1]) and (t[4pp+2],t[4pp+3])
                const ulonglong2 t2 =
                    *(const ulonglong2*)(g_t + (size_t)(n0 + i) * KK + 4 * pp);
                acc[i][0] = fma2(wA.x, t2.x, acc[i][0]);
                acc[i][1] = fma2(wA.y, t2.x, acc[i][1]);
                acc[i][2] = fma2(wB.x, t2.x, acc[i][2]);
                acc[i][3] = fma2(wB.y, t2.x, acc[i][3]);
                acc[i][0] = fma2(wC.x, t2.y, acc[i][0]);
                acc[i][1] = fma2(wC.y, t2.y, acc[i][1]);
                acc[i][2] = fma2(wD.x, t2.y, acc[i][2]);
                acc[i][3] = fma2(wD.y, t2.y, acc[i][3]);
            }
        }

        #pragma unroll
        for (int i = 0; i < 4; i++) {
            const float2 p0 = upk2(acc[i][0]);
            const float2 p1 = upk2(acc[i][1]);
            const float2 p2 = upk2(acc[i][2]);
            const float2 p3 = upk2(acc[i][3]);
            const float y0 = p0.x + p0.y + bo0;
            const float y1 = p1.x + p1.y + bo1;
            const float y2 = p2.x + p2.y + bo2;
            const float y3 = p3.x + p3.y + bo3;
            float* yr = g_y + (size_t)(n0 + i) * OO;
            *(float2*)(yr + 2 * lane)      = make_float2(y0, y1);
            *(float2*)(yr + AA + 2 * lane) = make_float2(y2, y3);
            ssum[0] += y0; ssq[0] += y0 * y0;
            ssum[1] += y1; ssq[1] += y1 * y1;
            ssum[2] += y2; ssq[2] += y2 * y2;
            ssum[3] += y3; ssq[3] += y3 * y3;
        }
    }

    __syncthreads();
    atomicAdd(&sstat[2 * lane],          ssum[0]);
    atomicAdd(&sstat[2 * lane + 1],      ssum[1]);
    atomicAdd(&sstat[AA + 2 * lane],     ssum[2]);
    atomicAdd(&sstat[AA + 2 * lane + 1], ssum[3]);
    atomicAdd(&sstat[OO + 2 * lane],          ssq[0]);
    atomicAdd(&sstat[OO + 2 * lane + 1],      ssq[1]);
    atomicAdd(&sstat[OO + AA + 2 * lane],     ssq[2]);
    atomicAdd(&sstat[OO + AA + 2 * lane + 1], ssq[3]);
    __syncthreads();
    if (tid < 2 * OO) atomicAdd(&g_stats1[tid], sstat[tid]);
}

// ---------------- kernel 3: finalize BN1 ----------------
__global__ void k_fin1(const float* __restrict__ gamma1,
                       const float* __restrict__ beta1) {
    int t = threadIdx.x;  // 128
    float mean = g_stats1[t] * (1.0f / NN);
    float var  = g_stats1[OO + t] * (1.0f / NN) - mean * mean;
    float sc = gamma1[t] * rsqrtf(var + EPSV);
    g_bn1[t] = sc;
    g_bn1[OO + t] = beta1[t] - mean * sc;
}

// ---------------- kernel 4: gate + BN2 stats (float4) ----------------
__global__ void __launch_bounds__(256)
k_gate() {
    __shared__ float sbn[2 * OO];
    __shared__ float sstat[2 * AA];
    int tid = threadIdx.x;
    sbn[tid] = g_bn1[tid];
    if (tid < 2 * AA) sstat[tid] = 0.0f;
    __syncthreads();

    const int total4 = NN * (AA / 4);            // 800000
    const int stride = gridDim.x * 256;          // 151552, mult of 16
    const int i0 = blockIdx.x * 256 + tid;
    const int f4 = i0 & 15;                      // invariant feature-quad
    const int fo = 4 * f4;

    const float4 scf = *(const float4*)(sbn + fo);
    const float4 shf = *(const float4*)(sbn + OO + fo);
    const float4 scc = *(const float4*)(sbn + AA + fo);
    const float4 shc = *(const float4*)(sbn + OO + AA + fo);

    float psum[4] = {0.f, 0.f, 0.f, 0.f};
    float psq[4]  = {0.f, 0.f, 0.f, 0.f};

    #pragma unroll 2
    for (int i = i0; i < total4; i += stride) {
        const int n = i >> 4;
        const float4 yf = *(const float4*)(g_y + (size_t)n * OO + fo);
        const float4 yc = *(const float4*)(g_y + (size_t)n * OO + AA + fo);
        float4 co;
        co.x = sigmoidf_(fmaf(yf.x, scf.x, shf.x)) * softplusf_(fmaf(yc.x, scc.x, shc.x));
        co.y = sigmoidf_(fmaf(yf.y, scf.y, shf.y)) * softplusf_(fmaf(yc.y, scc.y, shc.y));
        co.z = sigmoidf_(fmaf(yf.z, scf.z, shf.z)) * softplusf_(fmaf(yc.z, scc.z, shc.z));
        co.w = sigmoidf_(fmaf(yf.w, scf.w, shf.w)) * softplusf_(fmaf(yc.w, scc.w, shc.w));
        ((float4*)g_core)[i] = co;
        psum[0] += co.x; psq[0] += co.x * co.x;
        psum[1] += co.y; psq[1] += co.y * co.y;
        psum[2] += co.z; psq[2] += co.z * co.z;
        psum[3] += co.w; psq[3] += co.w * co.w;
    }
    #pragma unroll
    for (int c = 0; c < 4; c++) {
        atomicAdd(&sstat[fo + c], psum[c]);
        atomicAdd(&sstat[AA + fo + c], psq[c]);
    }
    __syncthreads();
    if (tid < 2 * AA) atomicAdd(&g_stats2[tid], sstat[tid]);
}

// ---------------- kernel 5: finalize BN2 ----------------
__global__ void k_fin2(const float* __restrict__ gamma2,
                       const float* __restrict__ beta2) {
    int t = threadIdx.x;  // 64
    float mean = g_stats2[t] * (1.0f / NN);
    float var  = g_stats2[AA + t] * (1.0f / NN) - mean * mean;
    float sc = gamma2[t] * rsqrtf(var + EPSV);
    g_bn2[t] = sc;
    g_bn2[AA + t] = beta2[t] - mean * sc;
}

// ---------------- kernel 6: out = softplus(BN2(core)) (float4) ----------------
__global__ void __launch_bounds__(256)
k_out(float* __restrict__ out) {
    __shared__ float sbn[2 * AA];
    int tid = threadIdx.x;
    if (tid < 2 * AA) sbn[tid] = g_bn2[tid];
    __syncthreads();

    const int total4 = NN * (AA / 4);
    const int stride = gridDim.x * 256;
    const int i0 = blockIdx.x * 256 + tid;
    const int fo = (i0 & 15) * 4;

    const float4 sc = *(const float4*)(sbn + fo);
    const float4 sh = *(const float4*)(sbn + AA + fo);

    #pragma unroll 2
    for (int i = i0; i < total4; i += stride) {
        const float4 c = ((const float4*)g_core)[i];
        float4 o;
        o.x = softplusf_(fmaf(c.x, sc.x, sh.x));
        o.y = softplusf_(fmaf(c.y, sc.y, sh.y));
        o.z = softplusf_(fmaf(c.z, sc.z, sh.z));
        o.w = softplusf_(fmaf(c.w, sc.w, sh.w));
        ((float4*)out)[i] = o;
    }
}

// ---------------- launcher ----------------
extern "C" void kernel_launch(void* const* d_in, const int* in_sizes, int n_in,
                              void* d_out, int out_size) {
    const float* atom   = (const float*)d_in[0];
    const float* nbrfea = (const float*)d_in[1];
    const int*   nbridx = (const int*)d_in[2];
    const float* bwi    = (const float*)d_in[3];
    const float* bwj    = (const float*)d_in[4];
    const float* W      = (const float*)d_in[5];
    const float* bias   = (const float*)d_in[6];
    const float* gamma1 = (const float*)d_in[7];
    const float* beta1  = (const float*)d_in[8];
    const float* gamma2 = (const float*)d_in[9];
    const float* beta2  = (const float*)d_in[10];
    float*       out    = (float*)d_out;

    const int smemG = SMEM_G_FLOATS * sizeof(float);  // ~81.5 KB
    cudaFuncSetAttribute(k_gemm, cudaFuncAttributeMaxDynamicSharedMemorySize, smemG);

    k_zero<<<1, 384>>>();
    k_feat<<<NN / 8, 256>>>(atom, nbrfea, nbridx, bwi, bwj);
    k_gemm<<<296, 256, smemG>>>(W, bias);
    k_fin1<<<1, 128>>>(gamma1, beta1);
    k_gate<<<592, 256>>>();
    k_fin2<<<1, 64>>>(gamma2, beta2);
    k_out<<<592, 256>>>(out);
}

// round 4
// speedup vs baseline: 1.4152x; 1.0026x over previous
#include <cuda_runtime.h>
#include <cstdint>

#define NN 50000
#define MM 24
#define AA 64
#define BB 32
#define KK 160   // 2A + B
#define OO 128   // 2A
#define EPSV 1e-5f

// ---------------- scratch (static __device__, zero-init at load) ----------------
__device__ float g_t[(size_t)NN * KK];      // 32 MB: concatenated gated features
__device__ float g_y[(size_t)NN * OO];      // 25.6 MB: pre-BN1 activations
__device__ float g_core[(size_t)NN * AA];   // 12.8 MB: gated core pre-BN2
__device__ float g_stats1[2 * OO];          // zeroed at load; re-zeroed by k_fin1
__device__ float g_stats2[2 * AA];          // zeroed at load; re-zeroed by k_fin2
__device__ float g_bn1[2 * OO];
__device__ float g_bn2[2 * AA];

// ---------------- f32x2 helpers ----------------
__device__ __forceinline__ unsigned long long fma2(unsigned long long a,
                                                   unsigned long long b,
                                                   unsigned long long c) {
    unsigned long long d;
    asm("fma.rn.f32x2 %0, %1, %2, %3;" : "=l"(d) : "l"(a), "l"(b), "l"(c));
    return d;
}
__device__ __forceinline__ float2 upk2(unsigned long long v) {
    float2 r;
    asm("mov.b64 {%0, %1}, %2;" : "=f"(r.x), "=f"(r.y) : "l"(v));
    return r;
}
__device__ __forceinline__ float sigmoidf_(float x) {
    return 1.0f / (1.0f + __expf(-x));
}
__device__ __forceinline__ float softplusf_(float x) {
    return fmaxf(x, 0.0f) + log1pf(__expf(-fabsf(x)));
}

// ---------------- kernel 1: gather/reduce -> t[n][160] ----------------
// one warp per node; idx/weights broadcast by shfl; loads front-batched in
// chunks of 12 to register arrays -> ~36 loads in flight per warp.
__global__ void __launch_bounds__(128)
k_feat(const float* __restrict__ atom,
       const float* __restrict__ nbrfea,
       const int* __restrict__ nbridx,
       const float* __restrict__ bwi,
       const float* __restrict__ bwj) {
    const int lane = threadIdx.x & 31;
    const int warp = threadIdx.x >> 5;
    const int n = blockIdx.x * 4 + warp;   // 12500*4 = 50000 exact

    float wm = 0.0f;
    int jv = 0;
    if (lane < MM) {
        wm = bwi[(size_t)n * MM + lane] * bwj[(size_t)n * MM + lane];
        jv = nbridx[(size_t)n * MM + lane];
    }
    float s = wm;
    #pragma unroll
    for (int o = 16; o; o >>= 1) s += __shfl_xor_sync(0xffffffffu, s, o);

    float a0 = 0.f, a1 = 0.f, bacc = 0.f;
    const float* nrow = nbrfea + (size_t)n * MM * BB;

    #pragma unroll
    for (int c = 0; c < 2; c++) {
        float2 ga[12];
        float  nb[12];
        float  wv[12];
        #pragma unroll
        for (int u = 0; u < 12; u++) {
            const int m = c * 12 + u;
            const int j = __shfl_sync(0xffffffffu, jv, m);
            wv[u] = __shfl_sync(0xffffffffu, wm, m);
            ga[u] = ((const float2*)(atom + (size_t)j * AA))[lane];
            nb[u] = nrow[m * BB + lane];
        }
        #pragma unroll
        for (int u = 0; u < 12; u++) {
            a0   = fmaf(wv[u], ga[u].x, a0);
            a1   = fmaf(wv[u], ga[u].y, a1);
            bacc = fmaf(wv[u], nb[u], bacc);
        }
    }

    const float2 aself = ((const float2*)(atom + (size_t)n * AA))[lane];
    float* t = g_t + (size_t)n * KK;
    ((float2*)t)[lane]        = make_float2(aself.x * s, aself.y * s); // t[0:64]
    ((float2*)(t + 64))[lane] = make_float2(a0, a1);                   // t[64:128]
    t[128 + lane] = bacc;                                              // t[128:160]
}

// ---------------- kernel 2: GEMM y = t @ W^T + b, fused BN1 stats ----------------
// k-pair packed f32x2: acc holds (even-k, odd-k) partials per output.
// sW4[p][q][0..3] = {W[2q][2p], W[2q][2p+1], W[2q+1][2p], W[2q+1][2p+1]}
#define SMEM_G_FLOATS (80 * 256 + OO + 2 * OO)
#define GW 8

__global__ void __launch_bounds__(256)
k_gemm(const float* __restrict__ W, const float* __restrict__ bias) {
    extern __shared__ float smem[];
    float* sW4   = smem;               // 20480
    float* sb    = sW4 + 80 * 256;     // 128
    float* sstat = sb + OO;            // 256

    const int tid  = threadIdx.x;
    const int lane = tid & 31;
    const int warp = tid >> 5;

    for (int i = tid; i < 80 * 256; i += 256) {
        const int p = i >> 8, r = i & 255, q = r >> 2, c = r & 3;
        const int o = 2 * q + (c >> 1);
        const int k = 2 * p + (c & 1);
        sW4[i] = W[o * KK + k];
    }
    if (tid < OO) sb[tid] = bias[tid];
    if (tid < 2 * OO) sstat[tid] = 0.0f;
    __syncthreads();

    // lane owns outputs {2l, 2l+1, 64+2l, 64+2l+1}
    const float bo0 = sb[2 * lane], bo1 = sb[2 * lane + 1];
    const float bo2 = sb[AA + 2 * lane], bo3 = sb[AA + 2 * lane + 1];

    float ssum[4] = {0.f, 0.f, 0.f, 0.f};
    float ssq[4]  = {0.f, 0.f, 0.f, 0.f};

    for (int g = blockIdx.x * GW + warp; g < NN / 4; g += gridDim.x * GW) {
        const int n0 = g * 4;

        unsigned long long acc[4][4];
        #pragma unroll
        for (int i = 0; i < 4; i++)
            #pragma unroll
            for (int c = 0; c < 4; c++) acc[i][c] = 0ull;

        #pragma unroll 2
        for (int pp = 0; pp < 40; pp++) {
            const ulonglong2* wp0 = (const ulonglong2*)(sW4 + (2 * pp) * 256);
            const ulonglong2* wp1 = (const ulonglong2*)(sW4 + (2 * pp + 1) * 256);
            const ulonglong2 wA = wp0[lane];
            const ulonglong2 wB = wp0[32 + lane];
            const ulonglong2 wC = wp1[lane];
            const ulonglong2 wD = wp1[32 + lane];

            #pragma unroll
            for (int i = 0; i < 4; i++) {
                const ulonglong2 t2 =
                    *(const ulonglong2*)(g_t + (size_t)(n0 + i) * KK + 4 * pp);
                acc[i][0] = fma2(wA.x, t2.x, acc[i][0]);
                acc[i][1] = fma2(wA.y, t2.x, acc[i][1]);
                acc[i][2] = fma2(wB.x, t2.x, acc[i][2]);
                acc[i][3] = fma2(wB.y, t2.x, acc[i][3]);
                acc[i][0] = fma2(wC.x, t2.y, acc[i][0]);
                acc[i][1] = fma2(wC.y, t2.y, acc[i][1]);
                acc[i][2] = fma2(wD.x, t2.y, acc[i][2]);
                acc[i][3] = fma2(wD.y, t2.y, acc[i][3]);
            }
        }

        #pragma unroll
        for (int i = 0; i < 4; i++) {
            const float2 p0 = upk2(acc[i][0]);
            const float2 p1 = upk2(acc[i][1]);
            const float2 p2 = upk2(acc[i][2]);
            const float2 p3 = upk2(acc[i][3]);
            const float y0 = p0.x + p0.y + bo0;
            const float y1 = p1.x + p1.y + bo1;
            const float y2 = p2.x + p2.y + bo2;
            const float y3 = p3.x + p3.y + bo3;
            float* yr = g_y + (size_t)(n0 + i) * OO;
            *(float2*)(yr + 2 * lane)      = make_float2(y0, y1);
            *(float2*)(yr + AA + 2 * lane) = make_float2(y2, y3);
            ssum[0] += y0; ssq[0] += y0 * y0;
            ssum[1] += y1; ssq[1] += y1 * y1;
            ssum[2] += y2; ssq[2] += y2 * y2;
            ssum[3] += y3; ssq[3] += y3 * y3;
        }
    }

    __syncthreads();
    atomicAdd(&sstat[2 * lane],          ssum[0]);
    atomicAdd(&sstat[2 * lane + 1],      ssum[1]);
    atomicAdd(&sstat[AA + 2 * lane],     ssum[2]);
    atomicAdd(&sstat[AA + 2 * lane + 1], ssum[3]);
    atomicAdd(&sstat[OO + 2 * lane],          ssq[0]);
    atomicAdd(&sstat[OO + 2 * lane + 1],      ssq[1]);
    atomicAdd(&sstat[OO + AA + 2 * lane],     ssq[2]);
    atomicAdd(&sstat[OO + AA + 2 * lane + 1], ssq[3]);
    __syncthreads();
    if (tid < 2 * OO) atomicAdd(&g_stats1[tid], sstat[tid]);
}

// ---------------- kernel 3: finalize BN1 (+ re-zero stats for next replay) ----------------
__global__ void k_fin1(const float* __restrict__ gamma1,
                       const float* __restrict__ beta1) {
    int t = threadIdx.x;  // 128
    float mean = g_stats1[t] * (1.0f / NN);
    float var  = g_stats1[OO + t] * (1.0f / NN) - mean * mean;
    float sc = gamma1[t] * rsqrtf(var + EPSV);
    g_bn1[t] = sc;
    g_bn1[OO + t] = beta1[t] - mean * sc;
    g_stats1[t] = 0.0f;
    g_stats1[OO + t] = 0.0f;
}

// ---------------- kernel 4: gate + BN2 stats (float4) ----------------
__global__ void __launch_bounds__(256)
k_gate() {
    __shared__ float sbn[2 * OO];
    __shared__ float sstat[2 * AA];
    int tid = threadIdx.x;
    sbn[tid] = g_bn1[tid];
    if (tid < 2 * AA) sstat[tid] = 0.0f;
    __syncthreads();

    const int total4 = NN * (AA / 4);            // 800000
    const int stride = gridDim.x * 256;
    const int i0 = blockIdx.x * 256 + tid;
    const int fo = 4 * (i0 & 15);                // invariant feature-quad

    const float4 scf = *(const float4*)(sbn + fo);
    const float4 shf = *(const float4*)(sbn + OO + fo);
    const float4 scc = *(const float4*)(sbn + AA + fo);
    const float4 shc = *(const float4*)(sbn + OO + AA + fo);

    float psum[4] = {0.f, 0.f, 0.f, 0.f};
    float psq[4]  = {0.f, 0.f, 0.f, 0.f};

    #pragma unroll 2
    for (int i = i0; i < total4; i += stride) {
        const int n = i >> 4;
        const float4 yf = *(const float4*)(g_y + (size_t)n * OO + fo);
        const float4 yc = *(const float4*)(g_y + (size_t)n * OO + AA + fo);
        float4 co;
        co.x = sigmoidf_(fmaf(yf.x, scf.x, shf.x)) * softplusf_(fmaf(yc.x, scc.x, shc.x));
        co.y = sigmoidf_(fmaf(yf.y, scf.y, shf.y)) * softplusf_(fmaf(yc.y, scc.y, shc.y));
        co.z = sigmoidf_(fmaf(yf.z, scf.z, shf.z)) * softplusf_(fmaf(yc.z, scc.z, shc.z));
        co.w = sigmoidf_(fmaf(yf.w, scf.w, shf.w)) * softplusf_(fmaf(yc.w, scc.w, shc.w));
        ((float4*)g_core)[i] = co;
        psum[0] += co.x; psq[0] += co.x * co.x;
        psum[1] += co.y; psq[1] += co.y * co.y;
        psum[2] += co.z; psq[2] += co.z * co.z;
        psum[3] += co.w; psq[3] += co.w * co.w;
    }
    #pragma unroll
    for (int c = 0; c < 4; c++) {
        atomicAdd(&sstat[fo + c], psum[c]);
        atomicAdd(&sstat[AA + fo + c], psq[c]);
    }
    __syncthreads();
    if (tid < 2 * AA) atomicAdd(&g_stats2[tid], sstat[tid]);
}

// ---------------- kernel 5: finalize BN2 (+ re-zero stats) ----------------
__global__ void k_fin2(const float* __restrict__ gamma2,
                       const float* __restrict__ beta2) {
    int t = threadIdx.x;  // 64
    float mean = g_stats2[t] * (1.0f / NN);
    float var  = g_stats2[AA + t] * (1.0f / NN) - mean * mean;
    float sc = gamma2[t] * rsqrtf(var + EPSV);
    g_bn2[t] = sc;
    g_bn2[AA + t] = beta2[t] - mean * sc;
    g_stats2[t] = 0.0f;
    g_stats2[AA + t] = 0.0f;
}

// ---------------- kernel 6: out = softplus(BN2(core)) (float4) ----------------
__global__ void __launch_bounds__(256)
k_out(float* __restrict__ out) {
    __shared__ float sbn[2 * AA];
    int tid = threadIdx.x;
    if (tid < 2 * AA) sbn[tid] = g_bn2[tid];
    __syncthreads();

    const int total4 = NN * (AA / 4);
    const int stride = gridDim.x * 256;
    const int i0 = blockIdx.x * 256 + tid;
    const int fo = (i0 & 15) * 4;

    const float4 sc = *(const float4*)(sbn + fo);
    const float4 sh = *(const float4*)(sbn + AA + fo);

    #pragma unroll 2
    for (int i = i0; i < total4; i += stride) {
        const float4 c = ((const float4*)g_core)[i];
        float4 o;
        o.x = softplusf_(fmaf(c.x, sc.x, sh.x));
        o.y = softplusf_(fmaf(c.y, sc.y, sh.y));
        o.z = softplusf_(fmaf(c.z, sc.z, sh.z));
        o.w = softplusf_(fmaf(c.w, sc.w, sh.w));
        ((float4*)out)[i] = o;
    }
}

// ---------------- launcher ----------------
extern "C" void kernel_launch(void* const* d_in, const int* in_sizes, int n_in,
                              void* d_out, int out_size) {
    const float* atom   = (const float*)d_in[0];
    const float* nbrfea = (const float*)d_in[1];
    const int*   nbridx = (const int*)d_in[2];
    const float* bwi    = (const float*)d_in[3];
    const float* bwj    = (const float*)d_in[4];
    const float* W      = (const float*)d_in[5];
    const float* bias   = (const float*)d_in[6];
    const float* gamma1 = (const float*)d_in[7];
    const float* beta1  = (const float*)d_in[8];
    const float* gamma2 = (const float*)d_in[9];
    const float* beta2  = (const float*)d_in[10];
    float*       out    = (float*)d_out;

    const int smemG = SMEM_G_FLOATS * sizeof(float);  // ~81.5 KB
    cudaFuncSetAttribute(k_gemm, cudaFuncAttributeMaxDynamicSharedMemorySize, smemG);

    k_feat<<<NN / 4, 128>>>(atom, nbrfea, nbridx, bwi, bwj);
    k_gemm<<<296, 256, smemG>>>(W, bias);
    k_fin1<<<1, 128>>>(gamma1, beta1);
    k_gate<<<592, 256>>>();
    k_fin2<<<1, 64>>>(gamma2, beta2);
    k_out<<<592, 256>>>(out);
}

// round 5
// speedup vs baseline: 1.8716x; 1.3225x over previous
#include <cuda_runtime.h>
#include <cuda_bf16.h>
#include <cstdint>

#define NN 50000
#define MM 24
#define AA 64
#define BB 32
#define KK 160   // 2A + B
#define OO 128   // 2A
#define EPSV 1e-5f
#define NTILES 391        // ceil(50000/128)
#define TPAD 168          // padded row stride (elements) for smem bf16 tiles

// ---------------- scratch (static __device__, zero-init at load) ----------------
__device__ float g_t[(size_t)NN * KK];      // 32 MB
__device__ float g_y[(size_t)NN * OO];      // 25.6 MB
__device__ float g_core[(size_t)NN * AA];   // 12.8 MB
__device__ __nv_bfloat16 g_wh[OO * KK];     // W hi plane
__device__ __nv_bfloat16 g_wl[OO * KK];     // W lo plane
__device__ float g_stats1[2 * OO];          // re-zeroed by k_fin1
__device__ float g_stats2[2 * AA];          // re-zeroed by k_fin2
__device__ float g_bn1[2 * OO];
__device__ float g_bn2[2 * AA];

// ---------------- helpers ----------------
__device__ __forceinline__ float sigmoidf_(float x) {
    return 1.0f / (1.0f + __expf(-x));
}
__device__ __forceinline__ float softplusf_(float x) {
    return fmaxf(x, 0.0f) + log1pf(__expf(-fabsf(x)));
}
__device__ __forceinline__ uint32_t smem_u32(const void* p) {
    return (uint32_t)__cvta_generic_to_shared(p);
}
__device__ __forceinline__ void ldsm_x4(uint32_t* r, uint32_t addr) {
    asm volatile("ldmatrix.sync.aligned.m8n8.x4.shared.b16 {%0,%1,%2,%3}, [%4];"
                 : "=r"(r[0]), "=r"(r[1]), "=r"(r[2]), "=r"(r[3]) : "r"(addr));
}
__device__ __forceinline__ void mma16816(float* d, const uint32_t* a,
                                         const uint32_t b0, const uint32_t b1) {
    asm volatile(
        "mma.sync.aligned.m16n8k16.row.col.f32.bf16.bf16.f32 "
        "{%0,%1,%2,%3}, {%4,%5,%6,%7}, {%8,%9}, {%0,%1,%2,%3};"
        : "+f"(d[0]), "+f"(d[1]), "+f"(d[2]), "+f"(d[3])
        : "r"(a[0]), "r"(a[1]), "r"(a[2]), "r"(a[3]), "r"(b0), "r"(b1));
}

// ---------------- kernel 1: gather/reduce -> t[n][160] ----------------
__global__ void __launch_bounds__(128)
k_feat(const float* __restrict__ atom,
       const float* __restrict__ nbrfea,
       const int* __restrict__ nbridx,
       const float* __restrict__ bwi,
       const float* __restrict__ bwj) {
    const int lane = threadIdx.x & 31;
    const int warp = threadIdx.x >> 5;
    const int n = blockIdx.x * 4 + warp;   // 12500*4 = 50000 exact

    float wm = 0.0f;
    int jv = 0;
    if (lane < MM) {
        wm = bwi[(size_t)n * MM + lane] * bwj[(size_t)n * MM + lane];
        jv = nbridx[(size_t)n * MM + lane];
    }
    float s = wm;
    #pragma unroll
    for (int o = 16; o; o >>= 1) s += __shfl_xor_sync(0xffffffffu, s, o);

    float a0 = 0.f, a1 = 0.f, bacc = 0.f;
    const float* nrow = nbrfea + (size_t)n * MM * BB;

    #pragma unroll
    for (int c = 0; c < 2; c++) {
        float2 ga[12];
        float  nb[12];
        float  wv[12];
        #pragma unroll
        for (int u = 0; u < 12; u++) {
            const int m = c * 12 + u;
            const int j = __shfl_sync(0xffffffffu, jv, m);
            wv[u] = __shfl_sync(0xffffffffu, wm, m);
            ga[u] = ((const float2*)(atom + (size_t)j * AA))[lane];
            nb[u] = nrow[m * BB + lane];
        }
        #pragma unroll
        for (int u = 0; u < 12; u++) {
            a0   = fmaf(wv[u], ga[u].x, a0);
            a1   = fmaf(wv[u], ga[u].y, a1);
            bacc = fmaf(wv[u], nb[u], bacc);
        }
    }

    const float2 aself = ((const float2*)(atom + (size_t)n * AA))[lane];
    float* t = g_t + (size_t)n * KK;
    ((float2*)t)[lane]        = make_float2(aself.x * s, aself.y * s);
    ((float2*)(t + 64))[lane] = make_float2(a0, a1);
    t[128 + lane] = bacc;
}

// ---------------- kernel 1b: split W into bf16 hi/lo planes ----------------
__global__ void k_wsplit(const float* __restrict__ W) {
    int i = blockIdx.x * 256 + threadIdx.x;
    if (i < OO * KK) {
        float x = W[i];
        __nv_bfloat16 h = __float2bfloat16(x);
        __nv_bfloat16 l = __float2bfloat16(x - __bfloat162float(h));
        g_wh[i] = h;
        g_wl[i] = l;
    }
}

// ---------------- kernel 2: tensor-core GEMM + fused BN1 stats ----------------
#define SMEM_G2 (4 * 128 * TPAD * 2 + (OO + 2 * OO) * 4)

__global__ void __launch_bounds__(256, 1)
k_gemm2(const float* __restrict__ bias) {
    extern __shared__ char smem_raw[];
    __nv_bfloat16* sAh = (__nv_bfloat16*)smem_raw;
    __nv_bfloat16* sAl = sAh + 128 * TPAD;
    __nv_bfloat16* sWh = sAl + 128 * TPAD;
    __nv_bfloat16* sWl = sWh + 128 * TPAD;
    float* sb    = (float*)(sWl + 128 * TPAD);
    float* sstat = sb + OO;

    const int tid  = threadIdx.x;
    const int lane = tid & 31;
    const int warp = tid >> 5;

    for (int i = tid; i < OO * KK / 2; i += 256) {
        const int row = i / (KK / 2);
        const int c2  = i % (KK / 2);
        ((uint32_t*)(sWh + row * TPAD))[c2] = ((const uint32_t*)g_wh)[i];
        ((uint32_t*)(sWl + row * TPAD))[c2] = ((const uint32_t*)g_wl)[i];
    }
    if (tid < OO) sb[tid] = bias[tid];
    sstat[tid] = 0.0f;

    float s_sum[16][2], s_sq[16][2];
    #pragma unroll
    for (int i = 0; i < 16; i++) {
        s_sum[i][0] = s_sum[i][1] = 0.f;
        s_sq[i][0]  = s_sq[i][1]  = 0.f;
    }

    const int wm = warp * 16;
    const int cbase = (lane & 3) * 2;
    const int rrow = lane >> 2;

    for (int tile = blockIdx.x; tile < NTILES; tile += gridDim.x) {
        const int n0 = tile * 128;
        __syncthreads();

        for (int i = tid; i < 128 * 40; i += 256) {
            const int r  = i / 40;
            const int c4 = (i % 40) * 4;
            const int n  = n0 + r;
            float4 v = make_float4(0.f, 0.f, 0.f, 0.f);
            if (n < NN) v = *(const float4*)(g_t + (size_t)n * KK + c4);
            __nv_bfloat16 h0 = __float2bfloat16(v.x);
            __nv_bfloat16 h1 = __float2bfloat16(v.y);
            __nv_bfloat16 h2 = __float2bfloat16(v.z);
            __nv_bfloat16 h3 = __float2bfloat16(v.w);
            __nv_bfloat16 l0 = __float2bfloat16(v.x - __bfloat162float(h0));
            __nv_bfloat16 l1 = __float2bfloat16(v.y - __bfloat162float(h1));
            __nv_bfloat16 l2 = __float2bfloat16(v.z - __bfloat162float(h2));
            __nv_bfloat16 l3 = __float2bfloat16(v.w - __bfloat162float(h3));
            __nv_bfloat162* dh = (__nv_bfloat162*)(sAh + r * TPAD + c4);
            __nv_bfloat162* dl = (__nv_bfloat162*)(sAl + r * TPAD + c4);
            dh[0] = __halves2bfloat162(h0, h1);
            dh[1] = __halves2bfloat162(h2, h3);
            dl[0] = __halves2bfloat162(l0, l1);
            dl[1] = __halves2bfloat162(l2, l3);
        }
        __syncthreads();

        float acc[16][4];
        #pragma unroll
        for (int i = 0; i < 16; i++)
            acc[i][0] = acc[i][1] = acc[i][2] = acc[i][3] = 0.f;

        #pragma unroll 1
        for (int kc = 0; kc < 10; kc++) {
            const int k0 = kc * 16;
            const int arow = wm + (lane & 15);
            const int acol = k0 + (lane >> 4) * 8;
            uint32_t ah[4], al[4];
            ldsm_x4(ah, smem_u32(sAh + arow * TPAD + acol));
            ldsm_x4(al, smem_u32(sAl + arow * TPAD + acol));

            const int brow_base = ((lane >> 4) & 1) * 8 + (lane & 7);
            const int bcol = k0 + ((lane >> 3) & 1) * 8;
            #pragma unroll
            for (int np = 0; np < 8; np++) {
                const int brow = np * 16 + brow_base;
                uint32_t bh[4], bl[4];
                ldsm_x4(bh, smem_u32(sWh + brow * TPAD + bcol));
                ldsm_x4(bl, smem_u32(sWl + brow * TPAD + bcol));
                mma16816(acc[2 * np],     ah, bh[0], bh[1]);
                mma16816(acc[2 * np],     al, bh[0], bh[1]);
                mma16816(acc[2 * np],     ah, bl[0], bl[1]);
                mma16816(acc[2 * np + 1], ah, bh[2], bh[3]);
                mma16816(acc[2 * np + 1], al, bh[2], bh[3]);
                mma16816(acc[2 * np + 1], ah, bl[2], bl[3]);
            }
        }

        const int r0 = n0 + wm + rrow;
        const bool v0 = (r0 < NN);
        const bool v1 = (r0 + 8 < NN);
        #pragma unroll
        for (int n8 = 0; n8 < 16; n8++) {
            const int col = n8 * 8 + cbase;
            const float b0 = sb[col], b1 = sb[col + 1];
            if (v0) {
                const float y0 = acc[n8][0] + b0;
                const float y1 = acc[n8][1] + b1;
                *(float2*)(g_y + (size_t)r0 * OO + col) = make_float2(y0, y1);
                s_sum[n8][0] += y0; s_sq[n8][0] += y0 * y0;
                s_sum[n8][1] += y1; s_sq[n8][1] += y1 * y1;
            }
            if (v1) {
                const float y2 = acc[n8][2] + b0;
                const float y3 = acc[n8][3] + b1;
                *(float2*)(g_y + (size_t)(r0 + 8) * OO + col) = make_float2(y2, y3);
                s_sum[n8][0] += y2; s_sq[n8][0] += y2 * y2;
                s_sum[n8][1] += y3; s_sq[n8][1] += y3 * y3;
            }
        }
    }

    #pragma unroll
    for (int n8 = 0; n8 < 16; n8++) {
        #pragma unroll
        for (int c = 0; c < 2; c++) {
            float v = s_sum[n8][c], q = s_sq[n8][c];
            #pragma unroll
            for (int mk = 4; mk <= 16; mk <<= 1) {
                v += __shfl_xor_sync(0xffffffffu, v, mk);
                q += __shfl_xor_sync(0xffffffffu, q, mk);
            }
            if (lane < 4) {
                const int col = n8 * 8 + lane * 2 + c;
                atomicAdd(&sstat[col], v);
                atomicAdd(&sstat[OO + col], q);
            }
        }
    }
    __syncthreads();
    atomicAdd(&g_stats1[tid], sstat[tid]);
}

// ---------------- kernel 3: finalize BN1 (+ re-zero stats) ----------------
__global__ void k_fin1(const float* __restrict__ gamma1,
                       const float* __restrict__ beta1) {
    int t = threadIdx.x;  // 128
    float mean = g_stats1[t] * (1.0f / NN);
    float var  = g_stats1[OO + t] * (1.0f / NN) - mean * mean;
    float sc = gamma1[t] * rsqrtf(var + EPSV);
    g_bn1[t] = sc;
    g_bn1[OO + t] = beta1[t] - mean * sc;
    g_stats1[t] = 0.0f;
    g_stats1[OO + t] = 0.0f;
}

// ---------------- kernel 4: gate + BN2 stats (float4) ----------------
__global__ void __launch_bounds__(256)
k_gate() {
    __shared__ float sbn[2 * OO];
    __shared__ float sstat[2 * AA];
    int tid = threadIdx.x;
    sbn[tid] = g_bn1[tid];
    if (tid < 2 * AA) sstat[tid] = 0.0f;
    __syncthreads();

    const int total4 = NN * (AA / 4);
    const int stride = gridDim.x * 256;
    const int i0 = blockIdx.x * 256 + tid;
    const int fo = 4 * (i0 & 15);

    const float4 scf = *(const float4*)(sbn + fo);
    const float4 shf = *(const float4*)(sbn + OO + fo);
    const float4 scc = *(const float4*)(sbn + AA + fo);
    const float4 shc = *(const float4*)(sbn + OO + AA + fo);

    float psum[4] = {0.f, 0.f, 0.f, 0.f};
    float psq[4]  = {0.f, 0.f, 0.f, 0.f};

    #pragma unroll 2
    for (int i = i0; i < total4; i += stride) {
        const int n = i >> 4;
        const float4 yf = *(const float4*)(g_y + (size_t)n * OO + fo);
        const float4 yc = *(const float4*)(g_y + (size_t)n * OO + AA + fo);
        float4 co;
        co.x = sigmoidf_(fmaf(yf.x, scf.x, shf.x)) * softplusf_(fmaf(yc.x, scc.x, shc.x));
        co.y = sigmoidf_(fmaf(yf.y, scf.y, shf.y)) * softplusf_(fmaf(yc.y, scc.y, shc.y));
        co.z = sigmoidf_(fmaf(yf.z, scf.z, shf.z)) * softplusf_(fmaf(yc.z, scc.z, shc.z));
        co.w = sigmoidf_(fmaf(yf.w, scf.w, shf.w)) * softplusf_(fmaf(yc.w, scc.w, shc.w));
        ((float4*)g_core)[i] = co;
        psum[0] += co.x; psq[0] += co.x * co.x;
        psum[1] += co.y; psq[1] += co.y * co.y;
        psum[2] += co.z; psq[2] += co.z * co.z;
        psum[3] += co.w; psq[3] += co.w * co.w;
    }
    #pragma unroll
    for (int c = 0; c < 4; c++) {
        atomicAdd(&sstat[fo + c], psum[c]);
        atomicAdd(&sstat[AA + fo + c], psq[c]);
    }
    __syncthreads();
    if (tid < 2 * AA) atomicAdd(&g_stats2[tid], sstat[tid]);
}

// ---------------- kernel 5: finalize BN2 (+ re-zero stats) ----------------
__global__ void k_fin2(const float* __restrict__ gamma2,
                       const float* __restrict__ beta2) {
    int t = threadIdx.x;  // 64
    float mean = g_stats2[t] * (1.0f / NN);
    float var  = g_stats2[AA + t] * (1.0f / NN) - mean * mean;
    float sc = gamma2[t] * rsqrtf(var + EPSV);
    g_bn2[t] = sc;
    g_bn2[AA + t] = beta2[t] - mean * sc;
    g_stats2[t] = 0.0f;
    g_stats2[AA + t] = 0.0f;
}

// ---------------- kernel 6: out = softplus(BN2(core)) (float4) ----------------
__global__ void __launch_bounds__(256)
k_out(float* __restrict__ out) {
    __shared__ float sbn[2 * AA];
    int tid = threadIdx.x;
    if (tid < 2 * AA) sbn[tid] = g_bn2[tid];
    __syncthreads();

    const int total4 = NN * (AA / 4);
    const int stride = gridDim.x * 256;
    const int i0 = blockIdx.x * 256 + tid;
    const int fo = (i0 & 15) * 4;

    const float4 sc = *(const float4*)(sbn + fo);
    const float4 sh = *(const float4*)(sbn + AA + fo);

    #pragma unroll 2
    for (int i = i0; i < total4; i += stride) {
        const float4 c = ((const float4*)g_core)[i];
        float4 o;
        o.x = softplusf_(fmaf(c.x, sc.x, sh.x));
        o.y = softplusf_(fmaf(c.y, sc.y, sh.y));
        o.z = softplusf_(fmaf(c.z, sc.z, sh.z));
        o.w = softplusf_(fmaf(c.w, sc.w, sh.w));
        ((float4*)out)[i] = o;
    }
}

// ---------------- launcher ----------------
extern "C" void kernel_launch(void* const* d_in, const int* in_sizes, int n_in,
                              void* d_out, int out_size) {
    const float* atom   = (const float*)d_in[0];
    const float* nbrfea = (const float*)d_in[1];
    const int*   nbridx = (const int*)d_in[2];
    const float* bwi    = (const float*)d_in[3];
    const float* bwj    = (const float*)d_in[4];
    const float* W      = (const float*)d_in[5];
    const float* bias   = (const float*)d_in[6];
    const float* gamma1 = (const float*)d_in[7];
    const float* beta1  = (const float*)d_in[8];
    const float* gamma2 = (const float*)d_in[9];
    const float* beta2  = (const float*)d_in[10];
    float*       out    = (float*)d_out;

    cudaFuncSetAttribute(k_gemm2, cudaFuncAttributeMaxDynamicSharedMemorySize, SMEM_G2);

    k_wsplit<<<(OO * KK + 255) / 256, 256>>>(W);
    k_feat<<<NN / 4, 128>>>(atom, nbrfea, nbridx, bwi, bwj);
    k_gemm2<<<148, 256, SMEM_G2>>>(bias);
    k_fin1<<<1, 128>>>(gamma1, beta1);
    k_gate<<<592, 256>>>();
    k_fin2<<<1, 64>>>(gamma2, beta2);
    k_out<<<592, 256>>>(out);
}

// round 6
// speedup vs baseline: 1.9856x; 1.0609x over previous
#include <cuda_runtime.h>
#include <cuda_bf16.h>
#include <cstdint>

#define NN 50000
#define MM 24
#define AA 64
#define BB 32
#define KK 160   // 2A + B
#define OO 128   // 2A
#define EPSV 1e-5f
#define NTILES 391        // ceil(50000/128)
#define TPAD 168          // padded row stride (elements) for smem bf16 tiles
#define NCTA 148
#define NTHR 384
#define TOT4 (NN * (AA / 4))      // 800000 float4 elements
#define GSTRIDE (NCTA * NTHR)     // 56832, divisible by 16

// ---------------- scratch (static __device__, zero-init at load) ----------------
__device__ float g_t[(size_t)NN * KK];      // 32 MB
__device__ float g_y[(size_t)NN * OO];      // 25.6 MB (L2-resident)
__device__ float g_core[(size_t)NN * AA];   // 12.8 MB (L2-resident)
__device__ float g_stats1[2 * OO];          // re-zeroed inside k_rest
__device__ float g_stats2[2 * AA];          // re-zeroed inside k_rest
__device__ unsigned g_count;                // barrier arrival counter
__device__ unsigned g_release;              // barrier release generation (monotonic)

// ---------------- helpers ----------------
__device__ __forceinline__ float softplus_fast(float x) {
    return fmaxf(x, 0.0f) + __logf(1.0f + __expf(-fabsf(x)));
}
__device__ __forceinline__ uint32_t smem_u32(const void* p) {
    return (uint32_t)__cvta_generic_to_shared(p);
}
__device__ __forceinline__ void ldsm_x4(uint32_t* r, uint32_t addr) {
    asm volatile("ldmatrix.sync.aligned.m8n8.x4.shared.b16 {%0,%1,%2,%3}, [%4];"
                 : "=r"(r[0]), "=r"(r[1]), "=r"(r[2]), "=r"(r[3]) : "r"(addr));
}
__device__ __forceinline__ void mma16816(float* d, const uint32_t* a,
                                         const uint32_t b0, const uint32_t b1) {
    asm volatile(
        "mma.sync.aligned.m16n8k16.row.col.f32.bf16.bf16.f32 "
        "{%0,%1,%2,%3}, {%4,%5,%6,%7}, {%8,%9}, {%0,%1,%2,%3};"
        : "+f"(d[0]), "+f"(d[1]), "+f"(d[2]), "+f"(d[3])
        : "r"(a[0]), "r"(a[1]), "r"(a[2]), "r"(a[3]), "r"(b0), "r"(b1));
}

// Replay-safe grid barrier: snapshot release before arriving; last arriver
// resets count and bumps release. Wrap-safe signed compare.
__device__ __forceinline__ void grid_barrier(int tid) {
    __syncthreads();
    if (tid == 0) {
        unsigned snap = atomicAdd(&g_release, 0u);
        __threadfence();
        unsigned old = atomicAdd(&g_count, 1u);
        if (old == NCTA - 1) {
            atomicExch(&g_count, 0u);
            __threadfence();
            atomicAdd(&g_release, 1u);
        } else {
            while ((int)(atomicAdd(&g_release, 0u) - snap) <= 0) { }
        }
    }
    __syncthreads();
    __threadfence();
}

// ---------------- kernel 1: gather/reduce -> t[n][160] ----------------
__global__ void __launch_bounds__(128)
k_feat(const float* __restrict__ atom,
       const float* __restrict__ nbrfea,
       const int* __restrict__ nbridx,
       const float* __restrict__ bwi,
       const float* __restrict__ bwj) {
    const int lane = threadIdx.x & 31;
    const int warp = threadIdx.x >> 5;
    const int n = blockIdx.x * 4 + warp;   // 12500*4 = 50000 exact

    float wm = 0.0f;
    int jv = 0;
    if (lane < MM) {
        wm = bwi[(size_t)n * MM + lane] * bwj[(size_t)n * MM + lane];
        jv = nbridx[(size_t)n * MM + lane];
    }
    float s = wm;
    #pragma unroll
    for (int o = 16; o; o >>= 1) s += __shfl_xor_sync(0xffffffffu, s, o);

    float a0 = 0.f, a1 = 0.f, bacc = 0.f;
    const float* nrow = nbrfea + (size_t)n * MM * BB;

    #pragma unroll
    for (int c = 0; c < 2; c++) {
        float2 ga[12];
        float  nb[12];
        float  wv[12];
        #pragma unroll
        for (int u = 0; u < 12; u++) {
            const int m = c * 12 + u;
            const int j = __shfl_sync(0xffffffffu, jv, m);
            wv[u] = __shfl_sync(0xffffffffu, wm, m);
            ga[u] = ((const float2*)(atom + (size_t)j * AA))[lane];
            nb[u] = nrow[m * BB + lane];
        }
        #pragma unroll
        for (int u = 0; u < 12; u++) {
            a0   = fmaf(wv[u], ga[u].x, a0);
            a1   = fmaf(wv[u], ga[u].y, a1);
            bacc = fmaf(wv[u], nb[u], bacc);
        }
    }

    const float2 aself = ((const float2*)(atom + (size_t)n * AA))[lane];
    float* t = g_t + (size_t)n * KK;
    ((float2*)t)[lane]        = make_float2(aself.x * s, aself.y * s);
    ((float2*)(t + 64))[lane] = make_float2(a0, a1);
    t[128 + lane] = bacc;
}

// ---------------- kernel 2: persistent fused GEMM + BN1 + gate + BN2 + out ----------------
#define SMEM_R (4 * 128 * TPAD * 2 + (OO + 2 * OO) * 4)

__global__ void __launch_bounds__(NTHR, 1)
k_rest(const float* __restrict__ W,
       const float* __restrict__ bias,
       const float* __restrict__ gamma1,
       const float* __restrict__ beta1,
       const float* __restrict__ gamma2,
       const float* __restrict__ beta2,
       float* __restrict__ out) {
    extern __shared__ char smem_raw[];
    __nv_bfloat16* sAh = (__nv_bfloat16*)smem_raw;
    __nv_bfloat16* sAl = sAh + 128 * TPAD;
    __nv_bfloat16* sWh = sAl + 128 * TPAD;
    __nv_bfloat16* sWl = sWh + 128 * TPAD;
    float* sb    = (float*)(sWl + 128 * TPAD);
    float* sstat = sb + OO;

    const int tid  = threadIdx.x;
    const int lane = tid & 31;
    const int warp = tid >> 5;

    // ======== prologue: load + split W directly from global ========
    for (int i = tid; i < OO * KK / 2; i += NTHR) {
        const int row = i / (KK / 2);
        const int c2  = i % (KK / 2);
        const float2 v = ((const float2*)W)[i];   // row-major pairs
        __nv_bfloat16 h0 = __float2bfloat16(v.x);
        __nv_bfloat16 h1 = __float2bfloat16(v.y);
        __nv_bfloat16 l0 = __float2bfloat16(v.x - __bfloat162float(h0));
        __nv_bfloat16 l1 = __float2bfloat16(v.y - __bfloat162float(h1));
        ((__nv_bfloat162*)(sWh + row * TPAD))[c2] = __halves2bfloat162(h0, h1);
        ((__nv_bfloat162*)(sWl + row * TPAD))[c2] = __halves2bfloat162(l0, l1);
    }
    if (tid < OO) sb[tid] = bias[tid];
    if (tid < 2 * OO) sstat[tid] = 0.0f;

    // ======== phase B: tensor-core GEMM y = t @ W^T + b, stats1 ========
    float s_sum[16][2], s_sq[16][2];
    #pragma unroll
    for (int i = 0; i < 16; i++) {
        s_sum[i][0] = s_sum[i][1] = 0.f;
        s_sq[i][0]  = s_sq[i][1]  = 0.f;
    }

    const int wm = warp * 16;              // only meaningful for warp < 8
    const int cbase = (lane & 3) * 2;
    const int rrow = lane >> 2;

    for (int tile = blockIdx.x; tile < NTILES; tile += gridDim.x) {
        const int n0 = tile * 128;
        __syncthreads();

        // cooperative A-tile load + hi/lo split (all 12 warps)
        for (int i = tid; i < 128 * 40; i += NTHR) {
            const int r  = i / 40;
            const int c4 = (i % 40) * 4;
            const int n  = n0 + r;
            float4 v = make_float4(0.f, 0.f, 0.f, 0.f);
            if (n < NN) v = *(const float4*)(g_t + (size_t)n * KK + c4);
            __nv_bfloat16 h0 = __float2bfloat16(v.x);
            __nv_bfloat16 h1 = __float2bfloat16(v.y);
            __nv_bfloat16 h2 = __float2bfloat16(v.z);
            __nv_bfloat16 h3 = __float2bfloat16(v.w);
            __nv_bfloat16 l0 = __float2bfloat16(v.x - __bfloat162float(h0));
            __nv_bfloat16 l1 = __float2bfloat16(v.y - __bfloat162float(h1));
            __nv_bfloat16 l2 = __float2bfloat16(v.z - __bfloat162float(h2));
            __nv_bfloat16 l3 = __float2bfloat16(v.w - __bfloat162float(h3));
            __nv_bfloat162* dh = (__nv_bfloat162*)(sAh + r * TPAD + c4);
            __nv_bfloat162* dl = (__nv_bfloat162*)(sAl + r * TPAD + c4);
            dh[0] = __halves2bfloat162(h0, h1);
            dh[1] = __halves2bfloat162(h2, h3);
            dl[0] = __halves2bfloat162(l0, l1);
            dl[1] = __halves2bfloat162(l2, l3);
        }
        __syncthreads();

        if (warp < 8) {
            float acc[16][4];
            #pragma unroll
            for (int i = 0; i < 16; i++)
                acc[i][0] = acc[i][1] = acc[i][2] = acc[i][3] = 0.f;

            #pragma unroll 1
            for (int kc = 0; kc < 10; kc++) {
                const int k0 = kc * 16;
                const int arow = wm + (lane & 15);
                const int acol = k0 + (lane >> 4) * 8;
                uint32_t ah[4], al[4];
                ldsm_x4(ah, smem_u32(sAh + arow * TPAD + acol));
                ldsm_x4(al, smem_u32(sAl + arow * TPAD + acol));

                const int brow_base = ((lane >> 4) & 1) * 8 + (lane & 7);
                const int bcol = k0 + ((lane >> 3) & 1) * 8;
                #pragma unroll
                for (int np = 0; np < 8; np++) {
                    const int brow = np * 16 + brow_base;
                    uint32_t bh[4], bl[4];
                    ldsm_x4(bh, smem_u32(sWh + brow * TPAD + bcol));
                    ldsm_x4(bl, smem_u32(sWl + brow * TPAD + bcol));
                    mma16816(acc[2 * np],     ah, bh[0], bh[1]);
                    mma16816(acc[2 * np],     al, bh[0], bh[1]);
                    mma16816(acc[2 * np],     ah, bl[0], bl[1]);
                    mma16816(acc[2 * np + 1], ah, bh[2], bh[3]);
                    mma16816(acc[2 * np + 1], al, bh[2], bh[3]);
                    mma16816(acc[2 * np + 1], ah, bl[2], bl[3]);
                }
            }

            const int r0 = n0 + wm + rrow;
            const bool v0 = (r0 < NN);
            const bool v1 = (r0 + 8 < NN);
            #pragma unroll
            for (int n8 = 0; n8 < 16; n8++) {
                const int col = n8 * 8 + cbase;
                const float b0 = sb[col], b1 = sb[col + 1];
                if (v0) {
                    const float y0 = acc[n8][0] + b0;
                    const float y1 = acc[n8][1] + b1;
                    *(float2*)(g_y + (size_t)r0 * OO + col) = make_float2(y0, y1);
                    s_sum[n8][0] += y0; s_sq[n8][0] += y0 * y0;
                    s_sum[n8][1] += y1; s_sq[n8][1] += y1 * y1;
                }
                if (v1) {
                    const float y2 = acc[n8][2] + b0;
                    const float y3 = acc[n8][3] + b1;
                    *(float2*)(g_y + (size_t)(r0 + 8) * OO + col) = make_float2(y2, y3);
                    s_sum[n8][0] += y2; s_sq[n8][0] += y2 * y2;
                    s_sum[n8][1] += y3; s_sq[n8][1] += y3 * y3;
                }
            }
        }
    }

    // stats1 reduce: shfl within warp, smem atomics, then global
    if (warp < 8) {
        #pragma unroll
        for (int n8 = 0; n8 < 16; n8++) {
            #pragma unroll
            for (int c = 0; c < 2; c++) {
                float v = s_sum[n8][c], q = s_sq[n8][c];
                #pragma unroll
                for (int mk = 4; mk <= 16; mk <<= 1) {
                    v += __shfl_xor_sync(0xffffffffu, v, mk);
                    q += __shfl_xor_sync(0xffffffffu, q, mk);
                }
                if (lane < 4) {
                    const int col = n8 * 8 + lane * 2 + c;
                    atomicAdd(&sstat[col], v);
                    atomicAdd(&sstat[OO + col], q);
                }
            }
        }
    }
    __syncthreads();
    if (tid < 2 * OO) atomicAdd(&g_stats1[tid], sstat[tid]);

    grid_barrier(tid);   // ---- barrier 1: stats1 complete, g_y visible ----

    // ======== phase C: BN1 params (local), gate, stats2 ========
    {
        float* f = (float*)smem_raw;
        float* sbn    = f;        // [scale128 | shift128]
        float* sstatC = f + 256;  // [sum64 | sq64]
        if (tid < OO) {
            const float mean = g_stats1[tid] * (1.0f / NN);
            const float var  = g_stats1[OO + tid] * (1.0f / NN) - mean * mean;
            const float sc = gamma1[tid] * rsqrtf(var + EPSV);
            sbn[tid] = sc;
            sbn[OO + tid] = beta1[tid] - mean * sc;
        }
        if (tid < 2 * AA) sstatC[tid] = 0.0f;
        __syncthreads();

        const int tidg = blockIdx.x * NTHR + tid;
        const int fo = 4 * (tidg & 15);
        const float4 scf = *(const float4*)(sbn + fo);
        const float4 scc = *(const float4*)(sbn + AA + fo);
        const float4 shf = *(const float4*)(sbn + OO + fo);
        const float4 shc = *(const float4*)(sbn + OO + AA + fo);

        float psum[4] = {0.f, 0.f, 0.f, 0.f};
        float psq[4]  = {0.f, 0.f, 0.f, 0.f};

        for (int base = tidg; base < TOT4; base += GSTRIDE * 8) {
            float4 yf[8], yc[8];
            #pragma unroll
            for (int u = 0; u < 8; u++) {
                const int i = base + u * GSTRIDE;
                if (i < TOT4) {
                    const int n = i >> 4;
                    yf[u] = *(const float4*)(g_y + (size_t)n * OO + fo);
                    yc[u] = *(const float4*)(g_y + (size_t)n * OO + AA + fo);
                }
            }
            #pragma unroll
            for (int u = 0; u < 8; u++) {
                const int i = base + u * GSTRIDE;
                if (i < TOT4) {
                    float4 co;
                    {
                        const float hf = fmaf(yf[u].x, scf.x, shf.x);
                        const float hc = fmaf(yc[u].x, scc.x, shc.x);
                        co.x = __fdividef(1.0f, 1.0f + __expf(-hf)) * softplus_fast(hc);
                    }
                    {
                        const float hf = fmaf(yf[u].y, scf.y, shf.y);
                        const float hc = fmaf(yc[u].y, scc.y, shc.y);
                        co.y = __fdividef(1.0f, 1.0f + __expf(-hf)) * softplus_fast(hc);
                    }
                    {
                        const float hf = fmaf(yf[u].z, scf.z, shf.z);
                        const float hc = fmaf(yc[u].z, scc.z, shc.z);
                        co.z = __fdividef(1.0f, 1.0f + __expf(-hf)) * softplus_fast(hc);
                    }
                    {
                        const float hf = fmaf(yf[u].w, scf.w, shf.w);
                        const float hc = fmaf(yc[u].w, scc.w, shc.w);
                        co.w = __fdividef(1.0f, 1.0f + __expf(-hf)) * softplus_fast(hc);
                    }
                    ((float4*)g_core)[i] = co;
                    psum[0] += co.x; psq[0] += co.x * co.x;
                    psum[1] += co.y; psq[1] += co.y * co.y;
                    psum[2] += co.z; psq[2] += co.z * co.z;
                    psum[3] += co.w; psq[3] += co.w * co.w;
                }
            }
        }
        #pragma unroll
        for (int c = 0; c < 4; c++) {
            atomicAdd(&sstatC[fo + c], psum[c]);
            atomicAdd(&sstatC[AA + fo + c], psq[c]);
        }
        __syncthreads();
        if (tid < 2 * AA) atomicAdd(&g_stats2[tid], sstatC[tid]);
    }

    grid_barrier(tid);   // ---- barrier 2: stats2 complete, g_core visible ----

    // ======== phase D: BN2 params (local), out = softplus ========
    {
        float* f = (float*)smem_raw;
        float* sbn2 = f;   // [scale64 | shift64]
        if (tid < AA) {
            const float mean = g_stats2[tid] * (1.0f / NN);
            const float var  = g_stats2[AA + tid] * (1.0f / NN) - mean * mean;
            const float sc = gamma2[tid] * rsqrtf(var + EPSV);
            sbn2[tid] = sc;
            sbn2[AA + tid] = beta2[tid] - mean * sc;
        }
        // safe to re-zero stats1 now (all reads happened before barrier 2)
        if (blockIdx.x == 0 && tid < 2 * OO) g_stats1[tid] = 0.0f;
        __syncthreads();

        const int tidg = blockIdx.x * NTHR + tid;
        const int fo = 4 * (tidg & 15);
        const float4 sc4 = *(const float4*)(sbn2 + fo);
        const float4 sh4 = *(const float4*)(sbn2 + AA + fo);

        for (int base = tidg; base < TOT4; base += GSTRIDE * 8) {
            float4 cv[8];
            #pragma unroll
            for (int u = 0; u < 8; u++) {
                const int i = base + u * GSTRIDE;
                if (i < TOT4) cv[u] = ((const float4*)g_core)[i];
            }
            #pragma unroll
            for (int u = 0; u < 8; u++) {
                const int i = base + u * GSTRIDE;
                if (i < TOT4) {
                    float4 o;
                    o.x = softplus_fast(fmaf(cv[u].x, sc4.x, sh4.x));
                    o.y = softplus_fast(fmaf(cv[u].y, sc4.y, sh4.y));
                    o.z = softplus_fast(fmaf(cv[u].z, sc4.z, sh4.z));
                    o.w = softplus_fast(fmaf(cv[u].w, sc4.w, sh4.w));
                    ((float4*)out)[i] = o;
                }
            }
        }
    }

    grid_barrier(tid);   // ---- barrier 3: all stats2 reads done ----
    if (blockIdx.x == 0 && tid < 2 * AA) g_stats2[tid] = 0.0f;
}

// ---------------- launcher ----------------
extern "C" void kernel_launch(void* const* d_in, const int* in_sizes, int n_in,
                              void* d_out, int out_size) {
    const float* atom   = (const float*)d_in[0];
    const float* nbrfea = (const float*)d_in[1];
    const int*   nbridx = (const int*)d_in[2];
    const float* bwi    = (const float*)d_in[3];
    const float* bwj    = (const float*)d_in[4];
    const float* W      = (const float*)d_in[5];
    const float* bias   = (const float*)d_in[6];
    const float* gamma1 = (const float*)d_in[7];
    const float* beta1  = (const float*)d_in[8];
    const float* gamma2 = (const float*)d_in[9];
    const float* beta2  = (const float*)d_in[10];
    float*       out    = (float*)d_out;

    cudaFuncSetAttribute(k_rest, cudaFuncAttributeMaxDynamicSharedMemorySize, SMEM_R);

    k_feat<<<NN / 4, 128>>>(atom, nbrfea, nbridx, bwi, bwj);
    k_rest<<<NCTA, NTHR, SMEM_R>>>(W, bias, gamma1, beta1, gamma2, beta2, out);
}